// round 4
// baseline (speedup 1.0000x reference)
#include <cuda_runtime.h>
#include <math.h>

// Problem constants
#define B_  4
#define S_  256
#define V_  64
#define H_  128
#define NH_ 8
#define DH_ 16
#define LP1_ 11
#define NL_ 3
#define BT_ (B_ * S_)          // 1024
#define ZSZ (BT_ * V_ * H_)    // 33,554,432 elements

// Scratch buffers (device globals: no allocation API used)
__device__ float g_adj[V_ * V_ * LP1_];
__device__ float g_zA[ZSZ];
__device__ float g_zB[ZSZ];
__device__ float g_qb[ZSZ];
__device__ float g_kb[ZSZ];
__device__ float g_vb[ZSZ];

// ---------------------------------------------------------------------------
// Kernel 0: adj = sigmoid(adjacency_logits)
// ---------------------------------------------------------------------------
__global__ void sigmoid_kernel(const float* __restrict__ logits) {
    int i = blockIdx.x * 256 + threadIdx.x;
    if (i < V_ * V_ * LP1_) {
        g_adj[i] = 1.0f / (1.0f + __expf(-logits[i]));
    }
}

// ---------------------------------------------------------------------------
// Kernel 1: causal input  z[b,t,i,h] = sum_s A[i,s] ve[s,h] + sum_l Bl[i,l] te[l,h]
// One block per (b,t). 256 threads.
// ---------------------------------------------------------------------------
__global__ void causal_kernel(const float* __restrict__ x,
                              const float* __restrict__ var_emb,
                              const float* __restrict__ temp_emb,
                              float* __restrict__ zout_base) {
    int bt = blockIdx.x;
    int b = bt / S_;
    int t = bt % S_;
    int tid = threadIdx.x;

    __shared__ float xw[LP1_][V_];        // xw[l][s] = x[b, t-l, s]
    __shared__ float Asm[V_][V_];         // A[i][s]
    __shared__ float Blsm[V_][LP1_ + 1];  // Bl[i][l] (padded)

    for (int e = tid; e < LP1_ * V_; e += 256) {
        int l = e / V_, s2 = e % V_;
        int tt = t - l;
        xw[l][s2] = (tt >= 0) ? x[(b * S_ + tt) * V_ + s2] : 0.0f;
    }
    __syncthreads();

    // A[i][s] = sum_l xw[l][s] * adj[s][i][l]
    for (int e = tid; e < V_ * V_; e += 256) {
        int i = e >> 6, s2 = e & 63;
        const float* ap = g_adj + (s2 * V_ + i) * LP1_;
        float acc = 0.0f;
#pragma unroll
        for (int l = 0; l < LP1_; l++) acc += xw[l][s2] * ap[l];
        Asm[i][s2] = acc;
    }
    // Bl[i][l] = sum_s xw[l][s] * adj[s][i][l]   (704 entries: grid-stride!)
    for (int e = tid; e < V_ * LP1_; e += 256) {
        int i = e / LP1_, l = e % LP1_;
        float acc = 0.0f;
        for (int s2 = 0; s2 < V_; s2++)
            acc += xw[l][s2] * g_adj[(s2 * V_ + i) * LP1_ + l];
        Blsm[i][l] = acc;
    }
    __syncthreads();

    float* zout = zout_base + (size_t)bt * V_ * H_;
    for (int o = tid; o < V_ * H_; o += 256) {
        int i = o >> 7, h = o & 127;
        float acc = 0.0f;
#pragma unroll 8
        for (int s2 = 0; s2 < V_; s2++)
            acc += Asm[i][s2] * __ldg(var_emb + s2 * H_ + h);
#pragma unroll
        for (int l = 0; l < LP1_; l++)
            acc += Blsm[i][l] * __ldg(temp_emb + l * H_ + h);
        zout[o] = acc;
    }
}

// ---------------------------------------------------------------------------
// Kernel 2: per-variable GEMM  out[bt,v,:] = in[bt,v,:] @ W_v + b_v
// Optional fused LayerNorm + exact GELU (mech layers).
// grid = (BT/64, V), 256 threads, dynamic smem = (H*H + 64*H)*4 = 98304 B
// ---------------------------------------------------------------------------
template <bool DO_LN>
__global__ void gemm_kernel(const float* __restrict__ in,
                            const float* __restrict__ Wbase,
                            const float* __restrict__ bbase,
                            const float* __restrict__ gbase,
                            const float* __restrict__ nbbase,
                            float* __restrict__ out,
                            int wstride, int bstride) {
    extern __shared__ __align__(16) float sm[];
    float* Wsm = sm;            // [128][128]
    float* As  = sm + H_ * H_;  // [64][128] — input tile, reused as output staging

    int tid = threadIdx.x;
    int v = blockIdx.y;
    int row0 = blockIdx.x * 64;

    const float* W = Wbase + (size_t)v * wstride;
    const float4* W4 = (const float4*)W;
    float4* Wsm4 = (float4*)Wsm;
    for (int i = tid; i < H_ * H_ / 4; i += 256) Wsm4[i] = W4[i];

    for (int i = tid; i < 64 * H_ / 4; i += 256) {
        int r = i >> 5;       // 32 float4 per row
        int c = i & 31;
        ((float4*)As)[i] =
            *(const float4*)(in + ((size_t)(row0 + r) * V_ + v) * H_ + c * 4);
    }
    __syncthreads();

    int ty = tid >> 4, tx = tid & 15;   // 16x16 thread grid
    float acc[4][8];
#pragma unroll
    for (int i = 0; i < 4; i++)
#pragma unroll
        for (int j = 0; j < 8; j++) acc[i][j] = 0.0f;

#pragma unroll 4
    for (int kk = 0; kk < H_; kk++) {
        float a0 = As[(ty * 4 + 0) * H_ + kk];
        float a1 = As[(ty * 4 + 1) * H_ + kk];
        float a2 = As[(ty * 4 + 2) * H_ + kk];
        float a3 = As[(ty * 4 + 3) * H_ + kk];
        float4 w0 = *(float4*)(Wsm + kk * H_ + tx * 8);
        float4 w1 = *(float4*)(Wsm + kk * H_ + tx * 8 + 4);
        float wv[8] = {w0.x, w0.y, w0.z, w0.w, w1.x, w1.y, w1.z, w1.w};
        float av[4] = {a0, a1, a2, a3};
#pragma unroll
        for (int i = 0; i < 4; i++)
#pragma unroll
            for (int j = 0; j < 8; j++) acc[i][j] += av[i] * wv[j];
    }

    const float* bias = bbase + (size_t)v * bstride;
    float bv[8];
#pragma unroll
    for (int j = 0; j < 8; j++) bv[j] = bias[tx * 8 + j];

    __syncthreads();  // done reading As as input
#pragma unroll
    for (int i = 0; i < 4; i++)
#pragma unroll
        for (int j = 0; j < 8; j++)
            As[(ty * 4 + i) * H_ + tx * 8 + j] = acc[i][j] + bv[j];
    __syncthreads();

    if (DO_LN) {
        int w = tid >> 5, lane = tid & 31;
        const float* g  = gbase  + (size_t)v * bstride;
        const float* nb = nbbase + (size_t)v * bstride;
        float4 gg = *(const float4*)(g  + lane * 4);
        float4 bb = *(const float4*)(nb + lane * 4);
        for (int r = w; r < 64; r += 8) {
            float4 vals = *(float4*)(As + r * H_ + lane * 4);
            float s = vals.x + vals.y + vals.z + vals.w;
#pragma unroll
            for (int off = 16; off; off >>= 1) s += __shfl_xor_sync(~0u, s, off);
            float mu = s * (1.0f / H_);
            float d0 = vals.x - mu, d1 = vals.y - mu, d2 = vals.z - mu, d3 = vals.w - mu;
            float sq = d0 * d0 + d1 * d1 + d2 * d2 + d3 * d3;
#pragma unroll
            for (int off = 16; off; off >>= 1) sq += __shfl_xor_sync(~0u, sq, off);
            float inv = rsqrtf(sq * (1.0f / H_) + 1e-5f);
            float y0 = d0 * inv * gg.x + bb.x;
            float y1 = d1 * inv * gg.y + bb.y;
            float y2 = d2 * inv * gg.z + bb.z;
            float y3 = d3 * inv * gg.w + bb.w;
            // exact GELU
            y0 = y0 * 0.5f * (1.0f + erff(y0 * 0.70710678118654752f));
            y1 = y1 * 0.5f * (1.0f + erff(y1 * 0.70710678118654752f));
            y2 = y2 * 0.5f * (1.0f + erff(y2 * 0.70710678118654752f));
            y3 = y3 * 0.5f * (1.0f + erff(y3 * 0.70710678118654752f));
            float4 o4 = make_float4(y0, y1, y2, y3);
            *(float4*)(out + ((size_t)(row0 + r) * V_ + v) * H_ + lane * 4) = o4;
        }
    } else {
        for (int e = tid; e < 64 * H_ / 4; e += 256) {
            int r = e >> 5, c = e & 31;
            *(float4*)(out + ((size_t)(row0 + r) * V_ + v) * H_ + c * 4) =
                ((float4*)As)[e];
        }
    }
}

// ---------------------------------------------------------------------------
// Kernel 3: attention per (b, v, head). S=256, DH=16. 256 threads = 8 warps.
// dynamic smem: q[256*16] + k[256*17] + v[256*17] + p[8*256] = 59392 B
// ---------------------------------------------------------------------------
__global__ void attn_kernel(const float* __restrict__ qg,
                            const float* __restrict__ kg,
                            const float* __restrict__ vg,
                            float* __restrict__ og) {
    int id = blockIdx.x;
    int n  = id % NH_;
    int vv = (id / NH_) % V_;
    int b  = id / (NH_ * V_);
    int tid = threadIdx.x;

    extern __shared__ __align__(16) float asm_[];
    float* qs = asm_;                  // [256][16]
    float* ks = qs + S_ * DH_;         // [256][17]
    float* vs = ks + S_ * 17;          // [256][17]
    float* ps = vs + S_ * 17;          // [8][256]

    size_t base = ((size_t)(b * S_) * V_ + vv) * H_ + n * DH_;
    const size_t rstride = (size_t)V_ * H_;

    for (int e = tid; e < S_ * DH_; e += 256) {
        int t = e >> 4, d = e & 15;
        size_t g = base + (size_t)t * rstride + d;
        qs[t * DH_ + d] = qg[g];
        ks[t * 17 + d]  = kg[g];
        vs[t * 17 + d]  = vg[g];
    }
    __syncthreads();

    int w = tid >> 5, lane = tid & 31;
    float* psw = ps + w * S_;

    for (int q = w; q < S_; q += 8) {
        float qr[DH_];
#pragma unroll
        for (int d = 0; d < DH_; d++) qr[d] = qs[q * DH_ + d];

        float sc[8];
        float m = -1e30f;
#pragma unroll
        for (int j = 0; j < 8; j++) {
            int key = lane + 32 * j;
            float acc = 0.0f;
#pragma unroll
            for (int d = 0; d < DH_; d++) acc += qr[d] * ks[key * 17 + d];
            acc *= 0.25f;  // 1/sqrt(16)
            sc[j] = acc;
            m = fmaxf(m, acc);
        }
#pragma unroll
        for (int off = 16; off; off >>= 1)
            m = fmaxf(m, __shfl_xor_sync(~0u, m, off));
        float lsum = 0.0f;
#pragma unroll
        for (int j = 0; j < 8; j++) {
            float p = __expf(sc[j] - m);
            lsum += p;
            psw[lane + 32 * j] = p;
        }
#pragma unroll
        for (int off = 16; off; off >>= 1)
            lsum += __shfl_xor_sync(~0u, lsum, off);
        float inv = 1.0f / lsum;
        __syncwarp();

        int d = lane & 15;
        int half = lane >> 4;
        float o = 0.0f;
        int k0 = half * 128;
#pragma unroll 8
        for (int key = k0; key < k0 + 128; key++)
            o += psw[key] * vs[key * 17 + d];
        o += __shfl_xor_sync(~0u, o, 16);
        o *= inv;
        if (lane < 16)
            og[base + (size_t)q * rstride + d] = o;
        __syncwarp();
    }
}

// ---------------------------------------------------------------------------
// Kernel 4: output head  pred[bt,v] = dot(oproj[bt,v,:], out_W[v,:]) + out_b[v]
// warp per output.
// ---------------------------------------------------------------------------
__global__ void outhead_kernel(const float* __restrict__ oproj,
                               const float* __restrict__ out_W,
                               const float* __restrict__ out_b,
                               float* __restrict__ pred) {
    int gw = (blockIdx.x * 256 + threadIdx.x) >> 5;
    int lane = threadIdx.x & 31;
    if (gw >= BT_ * V_) return;
    int v = gw % V_;
    const float* o = oproj + (size_t)gw * H_;
    const float* wp = out_W + v * H_;
    float4 a  = *(const float4*)(o + lane * 4);
    float4 ww = *(const float4*)(wp + lane * 4);
    float s = a.x * ww.x + a.y * ww.y + a.z * ww.z + a.w * ww.w;
#pragma unroll
    for (int off = 16; off; off >>= 1) s += __shfl_xor_sync(~0u, s, off);
    if (lane == 0) pred[gw] = s + out_b[v];
}

// ---------------------------------------------------------------------------
// Launch
// ---------------------------------------------------------------------------
extern "C" void kernel_launch(void* const* d_in, const int* in_sizes, int n_in,
                              void* d_out, int out_size) {
    const float* x       = (const float*)d_in[0];
    const float* adj_l   = (const float*)d_in[1];
    const float* var_emb = (const float*)d_in[2];
    const float* temp_emb= (const float*)d_in[3];
    const float* mech_W  = (const float*)d_in[4];
    const float* mech_b  = (const float*)d_in[5];
    const float* ln_g    = (const float*)d_in[6];
    const float* ln_b    = (const float*)d_in[7];
    const float* Wq      = (const float*)d_in[8];
    const float* Wk      = (const float*)d_in[9];
    const float* Wv      = (const float*)d_in[10];
    const float* Wo      = (const float*)d_in[11];
    const float* bq      = (const float*)d_in[12];
    const float* bk      = (const float*)d_in[13];
    const float* bv      = (const float*)d_in[14];
    const float* bo      = (const float*)d_in[15];
    const float* out_W   = (const float*)d_in[16];
    const float* out_b   = (const float*)d_in[17];
    float* pred = (float*)d_out;

    float *zA, *zB, *qb, *kb, *vb;
    cudaGetSymbolAddress((void**)&zA, g_zA);
    cudaGetSymbolAddress((void**)&zB, g_zB);
    cudaGetSymbolAddress((void**)&qb, g_qb);
    cudaGetSymbolAddress((void**)&kb, g_kb);
    cudaGetSymbolAddress((void**)&vb, g_vb);

    const int GEMM_SMEM = (H_ * H_ + 64 * H_) * 4;          // 98304
    const int ATTN_SMEM = (S_ * DH_ + 2 * S_ * 17 + 8 * S_) * 4;  // 59392
    cudaFuncSetAttribute((const void*)gemm_kernel<true>,
                         cudaFuncAttributeMaxDynamicSharedMemorySize, GEMM_SMEM);
    cudaFuncSetAttribute((const void*)gemm_kernel<false>,
                         cudaFuncAttributeMaxDynamicSharedMemorySize, GEMM_SMEM);
    cudaFuncSetAttribute((const void*)attn_kernel,
                         cudaFuncAttributeMaxDynamicSharedMemorySize, ATTN_SMEM);

    // 0. sigmoid(adjacency)
    sigmoid_kernel<<<(V_ * V_ * LP1_ + 255) / 256, 256>>>(adj_l);

    // 1. causal input -> zA
    causal_kernel<<<BT_, 256>>>(x, var_emb, temp_emb, zA);

    // 2. mech layers (Linear -> LN -> GELU), ping-pong zA/zB
    dim3 ggrid(BT_ / 64, V_);
    gemm_kernel<true><<<ggrid, 256, GEMM_SMEM>>>(
        zA, mech_W + 0 * H_ * H_, mech_b + 0 * H_, ln_g + 0 * H_, ln_b + 0 * H_,
        zB, NL_ * H_ * H_, NL_ * H_);
    gemm_kernel<true><<<ggrid, 256, GEMM_SMEM>>>(
        zB, mech_W + 1 * H_ * H_, mech_b + 1 * H_, ln_g + 1 * H_, ln_b + 1 * H_,
        zA, NL_ * H_ * H_, NL_ * H_);
    gemm_kernel<true><<<ggrid, 256, GEMM_SMEM>>>(
        zA, mech_W + 2 * H_ * H_, mech_b + 2 * H_, ln_g + 2 * H_, ln_b + 2 * H_,
        zB, NL_ * H_ * H_, NL_ * H_);

    // 3. Q/K/V projections from zB
    gemm_kernel<false><<<ggrid, 256, GEMM_SMEM>>>(zB, Wq, bq, nullptr, nullptr,
                                                  qb, H_ * H_, H_);
    gemm_kernel<false><<<ggrid, 256, GEMM_SMEM>>>(zB, Wk, bk, nullptr, nullptr,
                                                  kb, H_ * H_, H_);
    gemm_kernel<false><<<ggrid, 256, GEMM_SMEM>>>(zB, Wv, bv, nullptr, nullptr,
                                                  vb, H_ * H_, H_);

    // 4. attention -> zA
    attn_kernel<<<B_ * V_ * NH_, 256, ATTN_SMEM>>>(qb, kb, vb, zA);

    // 5. output projection -> qb
    gemm_kernel<false><<<ggrid, 256, GEMM_SMEM>>>(zA, Wo, bo, nullptr, nullptr,
                                                  qb, H_ * H_, H_);

    // 6. output head -> d_out
    outhead_kernel<<<(BT_ * V_ * 32 + 255) / 256, 256>>>(qb, out_W, out_b, pred);
}

// round 5
// speedup vs baseline: 1.0211x; 1.0211x over previous
#include <cuda_runtime.h>
#include <math.h>

// Problem constants
#define B_  4
#define S_  256
#define V_  64
#define H_  128
#define NH_ 8
#define DH_ 16
#define LP1_ 11
#define NL_ 3
#define BT_ (B_ * S_)          // 1024
#define ZSZ (BT_ * V_ * H_)    // 8,388,608 elements (33.5 MB)

// Internal activation layout: [v][bt][h]  (v-major => contiguous GEMM tiles)
__device__ float g_adj[V_ * V_ * LP1_];
__device__ float g_zA[ZSZ];
__device__ float g_zB[ZSZ];
__device__ float g_qb[ZSZ];
__device__ float g_kb[ZSZ];
__device__ float g_vb[ZSZ];

// ---------------------------------------------------------------------------
// Kernel 0: adj = sigmoid(adjacency_logits)
// ---------------------------------------------------------------------------
__global__ void sigmoid_kernel(const float* __restrict__ logits) {
    int i = blockIdx.x * 256 + threadIdx.x;
    if (i < V_ * V_ * LP1_) g_adj[i] = 1.0f / (1.0f + __expf(-logits[i]));
}

// ---------------------------------------------------------------------------
// Kernel 1: causal input.  One block per (b,t), 256 threads.
// z[i][bt][h] = sum_s A[i,s] ve[s,h] + sum_l Bl[i,l] te[l,h]
// dynamic smem: xw 704 + Asm 64*65 + Bl 64*12 + ve 64*128 + te 11*128
// ---------------------------------------------------------------------------
#define CAU_XW   0
#define CAU_ASM  (CAU_XW + LP1_ * 64)          // stride 65 (conflict-free)
#define CAU_BL   (CAU_ASM + 64 * 65)           // stride 12
#define CAU_VE   (CAU_BL + 64 * 12)
#define CAU_TE   (CAU_VE + 64 * 128)
#define CAU_SMEM ((CAU_TE + LP1_ * 128) * 4)

__global__ void causal_kernel(const float* __restrict__ x,
                              const float* __restrict__ var_emb,
                              const float* __restrict__ temp_emb,
                              float* __restrict__ zout) {
    extern __shared__ __align__(16) float cs[];
    float* xw  = cs + CAU_XW;
    float* Asm = cs + CAU_ASM;
    float* Bl  = cs + CAU_BL;
    float* ve  = cs + CAU_VE;
    float* te  = cs + CAU_TE;

    int bt = blockIdx.x;
    int b = bt / S_;
    int t = bt % S_;
    int tid = threadIdx.x;

    // loads
    for (int e = tid; e < LP1_ * 64; e += 256) {
        int l = e >> 6, s2 = e & 63;
        int tt = t - l;
        xw[l * 64 + s2] = (tt >= 0) ? x[(b * S_ + tt) * V_ + s2] : 0.0f;
    }
    for (int e = tid; e < 64 * 128 / 4; e += 256)
        ((float4*)ve)[e] = ((const float4*)var_emb)[e];
    for (int e = tid; e < LP1_ * 128 / 4; e += 256)
        ((float4*)te)[e] = ((const float4*)temp_emb)[e];
    __syncthreads();

    // A[i][s] = sum_l xw[l][s] * adj[s][i][l]
    for (int e = tid; e < 64 * 64; e += 256) {
        int i = e >> 6, s2 = e & 63;
        const float* ap = g_adj + (s2 * V_ + i) * LP1_;
        float acc = 0.0f;
#pragma unroll
        for (int l = 0; l < LP1_; l++) acc += xw[l * 64 + s2] * ap[l];
        Asm[i * 65 + s2] = acc;
    }
    // Bl[i][l] = sum_s xw[l][s] * adj[s][i][l]
    for (int e = tid; e < 64 * LP1_; e += 256) {
        int i = e / LP1_, l = e % LP1_;
        float acc = 0.0f;
        for (int s2 = 0; s2 < 64; s2++)
            acc += xw[l * 64 + s2] * g_adj[(s2 * V_ + i) * LP1_ + l];
        Bl[i * 12 + l] = acc;
    }
    __syncthreads();

    // z: thread -> (i = tid>>2, q = tid&3), owns h = j*16 + q*4 + c  (j 0..7, c 0..3)
    int i = tid >> 2, q = tid & 3;
    float4 acc[8];
#pragma unroll
    for (int j = 0; j < 8; j++) acc[j] = make_float4(0.f, 0.f, 0.f, 0.f);

    for (int s2 = 0; s2 < 64; s2++) {
        float a = Asm[i * 65 + s2];
        const float* vr = ve + s2 * 128 + q * 4;
#pragma unroll
        for (int j = 0; j < 8; j++) {
            float4 vv = *(const float4*)(vr + j * 16);
            acc[j].x += a * vv.x; acc[j].y += a * vv.y;
            acc[j].z += a * vv.z; acc[j].w += a * vv.w;
        }
    }
#pragma unroll
    for (int l = 0; l < LP1_; l++) {
        float bl = Bl[i * 12 + l];
        const float* tr = te + l * 128 + q * 4;
#pragma unroll
        for (int j = 0; j < 8; j++) {
            float4 vv = *(const float4*)(tr + j * 16);
            acc[j].x += bl * vv.x; acc[j].y += bl * vv.y;
            acc[j].z += bl * vv.z; acc[j].w += bl * vv.w;
        }
    }
    float* zr = zout + ((size_t)i * BT_ + bt) * H_ + q * 4;
#pragma unroll
    for (int j = 0; j < 8; j++) *(float4*)(zr + j * 16) = acc[j];
}

// ---------------------------------------------------------------------------
// Kernel 2: per-variable GEMM, 128x128 tile, 8x8 microtile, KC=32 double-buffered.
// MODE 0: +bias (QKV via blockIdx.z)   MODE 1: +bias,LN,GELU   MODE 2: +bias, out-head
// grid (BT/128, V [, 3]), 256 threads. smem = (2*32*132 + 2*32*128)*4 = 66560 B
// ---------------------------------------------------------------------------
#define AP_ 132
#define ABUF (32 * AP_)   // 4224
#define WBUF (32 * 128)   // 4096
#define GEMM_SMEM ((2 * ABUF + 2 * WBUF) * 4)

__device__ __forceinline__ void gemm_compute(const float* __restrict__ Ab,
                                             const float* __restrict__ Wb,
                                             float acc[8][8], int ty, int tx) {
#pragma unroll 8
    for (int kk = 0; kk < 32; kk++) {
        float4 a0 = *(const float4*)(Ab + kk * AP_ + ty * 8);
        float4 a1 = *(const float4*)(Ab + kk * AP_ + ty * 8 + 4);
        float4 b0 = *(const float4*)(Wb + kk * 128 + tx * 4);
        float4 b1 = *(const float4*)(Wb + kk * 128 + 64 + tx * 4);
        float a[8] = {a0.x, a0.y, a0.z, a0.w, a1.x, a1.y, a1.z, a1.w};
        float bb[8] = {b0.x, b0.y, b0.z, b0.w, b1.x, b1.y, b1.z, b1.w};
#pragma unroll
        for (int i = 0; i < 8; i++)
#pragma unroll
            for (int j = 0; j < 8; j++) acc[i][j] += a[i] * bb[j];
    }
}

template <int MODE>
__global__ __launch_bounds__(256, 2) void gemm2(
    const float* __restrict__ in,
    const float* __restrict__ W0, const float* __restrict__ W1,
    const float* __restrict__ W2,
    const float* __restrict__ Bi0, const float* __restrict__ Bi1,
    const float* __restrict__ Bi2,
    const float* __restrict__ G, const float* __restrict__ NB,
    float* O0, float* O1, float* O2,
    const float* __restrict__ OW, const float* __restrict__ OB,
    float* PRED, int wstride, int bstride) {
    extern __shared__ __align__(16) float sm[];
    float* Ast = sm;                  // [2][32][132]
    float* Wsm = sm + 2 * ABUF;       // [2][32][128]

    int tid = threadIdx.x;
    int v = blockIdx.y;
    int bt0 = blockIdx.x * 128;
    int z = blockIdx.z;

    const float* W    = (z == 0 ? W0 : (z == 1 ? W1 : W2)) + (size_t)v * wstride;
    const float* bias = (z == 0 ? Bi0 : (z == 1 ? Bi1 : Bi2)) + (size_t)v * bstride;
    float* out        = (z == 0 ? O0 : (z == 1 ? O1 : O2));
    const float* inp = in + ((size_t)v * BT_ + bt0) * H_;

    int ty = tid >> 4, tx = tid & 15;

    float acc[8][8];
#pragma unroll
    for (int i = 0; i < 8; i++)
#pragma unroll
        for (int j = 0; j < 8; j++) acc[i][j] = 0.0f;

    float4 la[4], lw[4];
    // prologue: chunk 0
#pragma unroll
    for (int t = 0; t < 4; t++) {
        int idx = tid + t * 256;
        int r = idx >> 3, c4 = idx & 7;
        la[t] = *(const float4*)(inp + (size_t)r * H_ + c4 * 4);
        int wr = idx >> 5, wc = idx & 31;
        lw[t] = *(const float4*)(W + wr * H_ + wc * 4);
    }
#pragma unroll
    for (int t = 0; t < 4; t++) {
        int idx = tid + t * 256;
        int r = idx >> 3, c4 = idx & 7;
        float* d = Ast;
        d[(c4 * 4 + 0) * AP_ + r] = la[t].x;
        d[(c4 * 4 + 1) * AP_ + r] = la[t].y;
        d[(c4 * 4 + 2) * AP_ + r] = la[t].z;
        d[(c4 * 4 + 3) * AP_ + r] = la[t].w;
        int wr = idx >> 5, wc = idx & 31;
        *(float4*)(Wsm + wr * 128 + wc * 4) = lw[t];
    }
    __syncthreads();

    for (int c = 0; c < 4; c++) {
        if (c < 3) {
            int k0 = (c + 1) * 32;
#pragma unroll
            for (int t = 0; t < 4; t++) {
                int idx = tid + t * 256;
                int r = idx >> 3, c4 = idx & 7;
                la[t] = *(const float4*)(inp + (size_t)r * H_ + k0 + c4 * 4);
                int wr = idx >> 5, wc = idx & 31;
                lw[t] = *(const float4*)(W + (k0 + wr) * H_ + wc * 4);
            }
        }
        gemm_compute(Ast + (c & 1) * ABUF, Wsm + (c & 1) * WBUF, acc, ty, tx);
        if (c < 3) {
            float* ad = Ast + ((c + 1) & 1) * ABUF;
            float* wd = Wsm + ((c + 1) & 1) * WBUF;
#pragma unroll
            for (int t = 0; t < 4; t++) {
                int idx = tid + t * 256;
                int r = idx >> 3, c4 = idx & 7;
                ad[(c4 * 4 + 0) * AP_ + r] = la[t].x;
                ad[(c4 * 4 + 1) * AP_ + r] = la[t].y;
                ad[(c4 * 4 + 2) * AP_ + r] = la[t].z;
                ad[(c4 * 4 + 3) * AP_ + r] = la[t].w;
                int wr = idx >> 5, wc = idx & 31;
                *(float4*)(wd + wr * 128 + wc * 4) = lw[t];
            }
            __syncthreads();
        }
    }

    // bias
    float4 bv0 = *(const float4*)(bias + tx * 4);
    float4 bv1 = *(const float4*)(bias + 64 + tx * 4);
    float bb[8] = {bv0.x, bv0.y, bv0.z, bv0.w, bv1.x, bv1.y, bv1.z, bv1.w};

    if (MODE == 0) {
        float* orow = out + ((size_t)v * BT_ + bt0 + ty * 8) * H_;
#pragma unroll
        for (int i = 0; i < 8; i++) {
            float4 o0 = make_float4(acc[i][0] + bb[0], acc[i][1] + bb[1],
                                    acc[i][2] + bb[2], acc[i][3] + bb[3]);
            float4 o1 = make_float4(acc[i][4] + bb[4], acc[i][5] + bb[5],
                                    acc[i][6] + bb[6], acc[i][7] + bb[7]);
            *(float4*)(orow + (size_t)i * H_ + tx * 4) = o0;
            *(float4*)(orow + (size_t)i * H_ + 64 + tx * 4) = o1;
        }
    } else if (MODE == 1) {
        const float* g  = G  + (size_t)v * bstride;
        const float* nb = NB + (size_t)v * bstride;
        float4 g0 = *(const float4*)(g + tx * 4);
        float4 g1 = *(const float4*)(g + 64 + tx * 4);
        float4 n0 = *(const float4*)(nb + tx * 4);
        float4 n1 = *(const float4*)(nb + 64 + tx * 4);
        float gv[8] = {g0.x, g0.y, g0.z, g0.w, g1.x, g1.y, g1.z, g1.w};
        float nv[8] = {n0.x, n0.y, n0.z, n0.w, n1.x, n1.y, n1.z, n1.w};
        float* orow = out + ((size_t)v * BT_ + bt0 + ty * 8) * H_;
#pragma unroll
        for (int i = 0; i < 8; i++) {
            float vals[8];
            float s = 0.0f;
#pragma unroll
            for (int j = 0; j < 8; j++) { vals[j] = acc[i][j] + bb[j]; s += vals[j]; }
            s += __shfl_xor_sync(0xffffffffu, s, 8);
            s += __shfl_xor_sync(0xffffffffu, s, 4);
            s += __shfl_xor_sync(0xffffffffu, s, 2);
            s += __shfl_xor_sync(0xffffffffu, s, 1);
            float mu = s * (1.0f / H_);
            float sq = 0.0f;
#pragma unroll
            for (int j = 0; j < 8; j++) { vals[j] -= mu; sq += vals[j] * vals[j]; }
            sq += __shfl_xor_sync(0xffffffffu, sq, 8);
            sq += __shfl_xor_sync(0xffffffffu, sq, 4);
            sq += __shfl_xor_sync(0xffffffffu, sq, 2);
            sq += __shfl_xor_sync(0xffffffffu, sq, 1);
            float inv = rsqrtf(sq * (1.0f / H_) + 1e-5f);
            float y[8];
#pragma unroll
            for (int j = 0; j < 8; j++) {
                float t2 = vals[j] * inv * gv[j] + nv[j];
                y[j] = t2 * 0.5f * (1.0f + erff(t2 * 0.70710678118654752f));
            }
            *(float4*)(orow + (size_t)i * H_ + tx * 4) =
                make_float4(y[0], y[1], y[2], y[3]);
            *(float4*)(orow + (size_t)i * H_ + 64 + tx * 4) =
                make_float4(y[4], y[5], y[6], y[7]);
        }
    } else {  // MODE 2: fused output head
        float4 w0 = *(const float4*)(OW + (size_t)v * H_ + tx * 4);
        float4 w1 = *(const float4*)(OW + (size_t)v * H_ + 64 + tx * 4);
        float ow[8] = {w0.x, w0.y, w0.z, w0.w, w1.x, w1.y, w1.z, w1.w};
        float ob = OB[v];
#pragma unroll
        for (int i = 0; i < 8; i++) {
            float s = 0.0f;
#pragma unroll
            for (int j = 0; j < 8; j++) s += (acc[i][j] + bb[j]) * ow[j];
            s += __shfl_xor_sync(0xffffffffu, s, 8);
            s += __shfl_xor_sync(0xffffffffu, s, 4);
            s += __shfl_xor_sync(0xffffffffu, s, 2);
            s += __shfl_xor_sync(0xffffffffu, s, 1);
            if (tx == 0) PRED[(size_t)(bt0 + ty * 8 + i) * V_ + v] = s + ob;
        }
    }
}

// ---------------------------------------------------------------------------
// Kernel 3: attention per (b, v, head). 256 threads = 8 warps.
// smem: qs[256*16] + ks[256*16] + vT[16*260] + psw[8*256]
// ---------------------------------------------------------------------------
#define VTP 260
#define ATTN_SMEM ((S_ * DH_ * 2 + DH_ * VTP + 8 * S_) * 4)

__global__ void attn_kernel(const float* __restrict__ qg,
                            const float* __restrict__ kg,
                            const float* __restrict__ vg,
                            float* __restrict__ og) {
    int id = blockIdx.x;
    int n  = id % NH_;
    int vv = (id / NH_) % V_;
    int b  = id / (NH_ * V_);
    int tid = threadIdx.x;

    extern __shared__ __align__(16) float asm_[];
    float* qs  = asm_;                    // [256][16]
    float* ks  = qs + S_ * DH_;           // [256][16]
    float* vT  = ks + S_ * DH_;           // [16][260]
    float* ps  = vT + DH_ * VTP;          // [8][256]

    size_t base = ((size_t)vv * BT_ + b * S_) * H_ + n * DH_;

    for (int e = tid; e < S_ * DH_; e += 256) {
        int t = e >> 4, d = e & 15;
        size_t g = base + (size_t)t * H_ + d;
        qs[t * DH_ + d] = qg[g];
        ks[t * DH_ + d] = kg[g];
        vT[d * VTP + t] = vg[g];
    }
    __syncthreads();

    int w = tid >> 5, lane = tid & 31;
    float* psw = ps + w * S_;

    for (int q = w; q < S_; q += 8) {
        float4 q0 = *(const float4*)(qs + q * DH_);
        float4 q1 = *(const float4*)(qs + q * DH_ + 4);
        float4 q2 = *(const float4*)(qs + q * DH_ + 8);
        float4 q3 = *(const float4*)(qs + q * DH_ + 12);

        float sc[8];
        float m = -1e30f;
#pragma unroll
        for (int j = 0; j < 8; j++) {
            int key = j * 32 + lane;
            const float* kr = ks + key * DH_;
            float4 k0 = *(const float4*)(kr);
            float4 k1 = *(const float4*)(kr + 4);
            float4 k2 = *(const float4*)(kr + 8);
            float4 k3 = *(const float4*)(kr + 12);
            float acc = q0.x * k0.x + q0.y * k0.y + q0.z * k0.z + q0.w * k0.w
                      + q1.x * k1.x + q1.y * k1.y + q1.z * k1.z + q1.w * k1.w
                      + q2.x * k2.x + q2.y * k2.y + q2.z * k2.z + q2.w * k2.w
                      + q3.x * k3.x + q3.y * k3.y + q3.z * k3.z + q3.w * k3.w;
            acc *= 0.25f;
            sc[j] = acc;
            m = fmaxf(m, acc);
        }
#pragma unroll
        for (int off = 16; off; off >>= 1)
            m = fmaxf(m, __shfl_xor_sync(0xffffffffu, m, off));
        float lsum = 0.0f;
#pragma unroll
        for (int j = 0; j < 8; j++) {
            float p = __expf(sc[j] - m);
            lsum += p;
            psw[j * 32 + lane] = p;
        }
#pragma unroll
        for (int off = 16; off; off >>= 1)
            lsum += __shfl_xor_sync(0xffffffffu, lsum, off);
        float inv = 1.0f / lsum;
        __syncwarp();

        int d = lane & 15;
        int half = lane >> 4;
        const float* vrow = vT + d * VTP + half * 128;
        const float* prow = psw + half * 128;
        float o = 0.0f;
#pragma unroll 8
        for (int it = 0; it < 32; it++) {
            float4 pv = *(const float4*)(prow + it * 4);
            float4 vv4 = *(const float4*)(vrow + it * 4);
            o += pv.x * vv4.x + pv.y * vv4.y + pv.z * vv4.z + pv.w * vv4.w;
        }
        o += __shfl_xor_sync(0xffffffffu, o, 16);
        o *= inv;
        if (lane < 16) og[base + (size_t)q * H_ + d] = o;
        __syncwarp();
    }
}

// ---------------------------------------------------------------------------
// Launch
// ---------------------------------------------------------------------------
extern "C" void kernel_launch(void* const* d_in, const int* in_sizes, int n_in,
                              void* d_out, int out_size) {
    const float* x       = (const float*)d_in[0];
    const float* adj_l   = (const float*)d_in[1];
    const float* var_emb = (const float*)d_in[2];
    const float* temp_emb= (const float*)d_in[3];
    const float* mech_W  = (const float*)d_in[4];
    const float* mech_b  = (const float*)d_in[5];
    const float* ln_g    = (const float*)d_in[6];
    const float* ln_b    = (const float*)d_in[7];
    const float* Wq      = (const float*)d_in[8];
    const float* Wk      = (const float*)d_in[9];
    const float* Wv      = (const float*)d_in[10];
    const float* Wo      = (const float*)d_in[11];
    const float* bq      = (const float*)d_in[12];
    const float* bk      = (const float*)d_in[13];
    const float* bv      = (const float*)d_in[14];
    const float* bo      = (const float*)d_in[15];
    const float* out_W   = (const float*)d_in[16];
    const float* out_b   = (const float*)d_in[17];
    float* pred = (float*)d_out;

    float *zA, *zB, *qb, *kb, *vb;
    cudaGetSymbolAddress((void**)&zA, g_zA);
    cudaGetSymbolAddress((void**)&zB, g_zB);
    cudaGetSymbolAddress((void**)&qb, g_qb);
    cudaGetSymbolAddress((void**)&kb, g_kb);
    cudaGetSymbolAddress((void**)&vb, g_vb);

    cudaFuncSetAttribute((const void*)gemm2<0>,
                         cudaFuncAttributeMaxDynamicSharedMemorySize, GEMM_SMEM);
    cudaFuncSetAttribute((const void*)gemm2<1>,
                         cudaFuncAttributeMaxDynamicSharedMemorySize, GEMM_SMEM);
    cudaFuncSetAttribute((const void*)gemm2<2>,
                         cudaFuncAttributeMaxDynamicSharedMemorySize, GEMM_SMEM);
    cudaFuncSetAttribute((const void*)causal_kernel,
                         cudaFuncAttributeMaxDynamicSharedMemorySize, CAU_SMEM);
    cudaFuncSetAttribute((const void*)attn_kernel,
                         cudaFuncAttributeMaxDynamicSharedMemorySize, ATTN_SMEM);

    // 0. sigmoid(adjacency)
    sigmoid_kernel<<<(V_ * V_ * LP1_ + 255) / 256, 256>>>(adj_l);

    // 1. causal input -> zA  ([v][bt][h] layout)
    causal_kernel<<<BT_, 256, CAU_SMEM>>>(x, var_emb, temp_emb, zA);

    // 2. mech layers: Linear -> LN -> GELU
    dim3 ggrid(BT_ / 128, V_, 1);
    const int WS = NL_ * H_ * H_, BS = NL_ * H_;
    gemm2<1><<<ggrid, 256, GEMM_SMEM>>>(zA,
        mech_W + 0 * H_ * H_, nullptr, nullptr,
        mech_b + 0 * H_, nullptr, nullptr,
        ln_g + 0 * H_, ln_b + 0 * H_,
        zB, nullptr, nullptr, nullptr, nullptr, nullptr, WS, BS);
    gemm2<1><<<ggrid, 256, GEMM_SMEM>>>(zB,
        mech_W + 1 * H_ * H_, nullptr, nullptr,
        mech_b + 1 * H_, nullptr, nullptr,
        ln_g + 1 * H_, ln_b + 1 * H_,
        zA, nullptr, nullptr, nullptr, nullptr, nullptr, WS, BS);
    gemm2<1><<<ggrid, 256, GEMM_SMEM>>>(zA,
        mech_W + 2 * H_ * H_, nullptr, nullptr,
        mech_b + 2 * H_, nullptr, nullptr,
        ln_g + 2 * H_, ln_b + 2 * H_,
        zB, nullptr, nullptr, nullptr, nullptr, nullptr, WS, BS);

    // 3. Q/K/V projections in one launch (blockIdx.z selects)
    dim3 qkvgrid(BT_ / 128, V_, 3);
    gemm2<0><<<qkvgrid, 256, GEMM_SMEM>>>(zB,
        Wq, Wk, Wv, bq, bk, bv, nullptr, nullptr,
        qb, kb, vb, nullptr, nullptr, nullptr, H_ * H_, H_);

    // 4. attention -> zA
    attn_kernel<<<B_ * V_ * NH_, 256, ATTN_SMEM>>>(qb, kb, vb, zA);

    // 5. Wo projection + fused output head -> pred
    gemm2<2><<<ggrid, 256, GEMM_SMEM>>>(zA,
        Wo, nullptr, nullptr, bo, nullptr, nullptr, nullptr, nullptr,
        nullptr, nullptr, nullptr, out_W, out_b, pred, H_ * H_, H_);
}

// round 6
// speedup vs baseline: 1.9711x; 1.9304x over previous
#include <cuda_runtime.h>
#include <math.h>

// Problem constants
#define B_  4
#define S_  256
#define V_  64
#define H_  128
#define NH_ 8
#define DH_ 16
#define LP1_ 11
#define NL_ 3
#define BT_ (B_ * S_)          // 1024
#define ZSZ (BT_ * V_ * H_)    // 8,388,608 elements (33.5 MB)

// Internal activation layout: [v][bt][h]  (v-major => contiguous GEMM tiles)
__device__ float g_adj[V_ * V_ * LP1_];
__device__ float g_zA[ZSZ];
__device__ float g_zB[ZSZ];
__device__ float g_qb[ZSZ];
__device__ float g_kb[ZSZ];
__device__ float g_vb[ZSZ];

// ---------------------------------------------------------------------------
// Kernel 0: adj = sigmoid(adjacency_logits)
// ---------------------------------------------------------------------------
__global__ void sigmoid_kernel(const float* __restrict__ logits) {
    int i = blockIdx.x * 256 + threadIdx.x;
    if (i < V_ * V_ * LP1_) g_adj[i] = 1.0f / (1.0f + __expf(-logits[i]));
}

// ---------------------------------------------------------------------------
// Kernel 1: causal input.  One block per (b,t), 256 threads.
// ---------------------------------------------------------------------------
#define CAU_XW   0
#define CAU_ASM  (CAU_XW + LP1_ * 64)          // stride 65 (conflict-free)
#define CAU_BL   (CAU_ASM + 64 * 65)           // stride 12
#define CAU_VE   (CAU_BL + 64 * 12)
#define CAU_TE   (CAU_VE + 64 * 128)
#define CAU_SMEM ((CAU_TE + LP1_ * 128) * 4)

__global__ void causal_kernel(const float* __restrict__ x,
                              const float* __restrict__ var_emb,
                              const float* __restrict__ temp_emb,
                              float* __restrict__ zout) {
    extern __shared__ __align__(16) float cs[];
    float* xw  = cs + CAU_XW;
    float* Asm = cs + CAU_ASM;
    float* Bl  = cs + CAU_BL;
    float* ve  = cs + CAU_VE;
    float* te  = cs + CAU_TE;

    int bt = blockIdx.x;
    int b = bt / S_;
    int t = bt % S_;
    int tid = threadIdx.x;

    for (int e = tid; e < LP1_ * 64; e += 256) {
        int l = e >> 6, s2 = e & 63;
        int tt = t - l;
        xw[l * 64 + s2] = (tt >= 0) ? x[(b * S_ + tt) * V_ + s2] : 0.0f;
    }
    for (int e = tid; e < 64 * 128 / 4; e += 256)
        ((float4*)ve)[e] = ((const float4*)var_emb)[e];
    for (int e = tid; e < LP1_ * 128 / 4; e += 256)
        ((float4*)te)[e] = ((const float4*)temp_emb)[e];
    __syncthreads();

    for (int e = tid; e < 64 * 64; e += 256) {
        int i = e >> 6, s2 = e & 63;
        const float* ap = g_adj + (s2 * V_ + i) * LP1_;
        float acc = 0.0f;
#pragma unroll
        for (int l = 0; l < LP1_; l++) acc += xw[l * 64 + s2] * ap[l];
        Asm[i * 65 + s2] = acc;
    }
    for (int e = tid; e < 64 * LP1_; e += 256) {
        int i = e / LP1_, l = e % LP1_;
        float acc = 0.0f;
        for (int s2 = 0; s2 < 64; s2++)
            acc += xw[l * 64 + s2] * g_adj[(s2 * V_ + i) * LP1_ + l];
        Bl[i * 12 + l] = acc;
    }
    __syncthreads();

    int i = tid >> 2, q = tid & 3;
    float4 acc[8];
#pragma unroll
    for (int j = 0; j < 8; j++) acc[j] = make_float4(0.f, 0.f, 0.f, 0.f);

    for (int s2 = 0; s2 < 64; s2++) {
        float a = Asm[i * 65 + s2];
        const float* vr = ve + s2 * 128 + q * 4;
#pragma unroll
        for (int j = 0; j < 8; j++) {
            float4 vv = *(const float4*)(vr + j * 16);
            acc[j].x += a * vv.x; acc[j].y += a * vv.y;
            acc[j].z += a * vv.z; acc[j].w += a * vv.w;
        }
    }
#pragma unroll
    for (int l = 0; l < LP1_; l++) {
        float bl = Bl[i * 12 + l];
        const float* tr = te + l * 128 + q * 4;
#pragma unroll
        for (int j = 0; j < 8; j++) {
            float4 vv = *(const float4*)(tr + j * 16);
            acc[j].x += bl * vv.x; acc[j].y += bl * vv.y;
            acc[j].z += bl * vv.z; acc[j].w += bl * vv.w;
        }
    }
    float* zr = zout + ((size_t)i * BT_ + bt) * H_ + q * 4;
#pragma unroll
    for (int j = 0; j < 8; j++) *(float4*)(zr + j * 16) = acc[j];
}

// ---------------------------------------------------------------------------
// Kernel 2: per-variable GEMM (unchanged from R5 - proven 67.8us/launch)
// ---------------------------------------------------------------------------
#define AP_ 132
#define ABUF (32 * AP_)   // 4224
#define WBUF (32 * 128)   // 4096
#define GEMM_SMEM ((2 * ABUF + 2 * WBUF) * 4)

__device__ __forceinline__ void gemm_compute(const float* __restrict__ Ab,
                                             const float* __restrict__ Wb,
                                             float acc[8][8], int ty, int tx) {
#pragma unroll 8
    for (int kk = 0; kk < 32; kk++) {
        float4 a0 = *(const float4*)(Ab + kk * AP_ + ty * 8);
        float4 a1 = *(const float4*)(Ab + kk * AP_ + ty * 8 + 4);
        float4 b0 = *(const float4*)(Wb + kk * 128 + tx * 4);
        float4 b1 = *(const float4*)(Wb + kk * 128 + 64 + tx * 4);
        float a[8] = {a0.x, a0.y, a0.z, a0.w, a1.x, a1.y, a1.z, a1.w};
        float bb[8] = {b0.x, b0.y, b0.z, b0.w, b1.x, b1.y, b1.z, b1.w};
#pragma unroll
        for (int i = 0; i < 8; i++)
#pragma unroll
            for (int j = 0; j < 8; j++) acc[i][j] += a[i] * bb[j];
    }
}

template <int MODE>
__global__ __launch_bounds__(256, 2) void gemm2(
    const float* __restrict__ in,
    const float* __restrict__ W0, const float* __restrict__ W1,
    const float* __restrict__ W2,
    const float* __restrict__ Bi0, const float* __restrict__ Bi1,
    const float* __restrict__ Bi2,
    const float* __restrict__ G, const float* __restrict__ NB,
    float* O0, float* O1, float* O2,
    const float* __restrict__ OW, const float* __restrict__ OB,
    float* PRED, int wstride, int bstride) {
    extern __shared__ __align__(16) float sm[];
    float* Ast = sm;
    float* Wsm = sm + 2 * ABUF;

    int tid = threadIdx.x;
    int v = blockIdx.y;
    int bt0 = blockIdx.x * 128;
    int z = blockIdx.z;

    const float* W    = (z == 0 ? W0 : (z == 1 ? W1 : W2)) + (size_t)v * wstride;
    const float* bias = (z == 0 ? Bi0 : (z == 1 ? Bi1 : Bi2)) + (size_t)v * bstride;
    float* out        = (z == 0 ? O0 : (z == 1 ? O1 : O2));
    const float* inp = in + ((size_t)v * BT_ + bt0) * H_;

    int ty = tid >> 4, tx = tid & 15;

    float acc[8][8];
#pragma unroll
    for (int i = 0; i < 8; i++)
#pragma unroll
        for (int j = 0; j < 8; j++) acc[i][j] = 0.0f;

    float4 la[4], lw[4];
#pragma unroll
    for (int t = 0; t < 4; t++) {
        int idx = tid + t * 256;
        int r = idx >> 3, c4 = idx & 7;
        la[t] = *(const float4*)(inp + (size_t)r * H_ + c4 * 4);
        int wr = idx >> 5, wc = idx & 31;
        lw[t] = *(const float4*)(W + wr * H_ + wc * 4);
    }
#pragma unroll
    for (int t = 0; t < 4; t++) {
        int idx = tid + t * 256;
        int r = idx >> 3, c4 = idx & 7;
        float* d = Ast;
        d[(c4 * 4 + 0) * AP_ + r] = la[t].x;
        d[(c4 * 4 + 1) * AP_ + r] = la[t].y;
        d[(c4 * 4 + 2) * AP_ + r] = la[t].z;
        d[(c4 * 4 + 3) * AP_ + r] = la[t].w;
        int wr = idx >> 5, wc = idx & 31;
        *(float4*)(Wsm + wr * 128 + wc * 4) = lw[t];
    }
    __syncthreads();

    for (int c = 0; c < 4; c++) {
        if (c < 3) {
            int k0 = (c + 1) * 32;
#pragma unroll
            for (int t = 0; t < 4; t++) {
                int idx = tid + t * 256;
                int r = idx >> 3, c4 = idx & 7;
                la[t] = *(const float4*)(inp + (size_t)r * H_ + k0 + c4 * 4);
                int wr = idx >> 5, wc = idx & 31;
                lw[t] = *(const float4*)(W + (k0 + wr) * H_ + wc * 4);
            }
        }
        gemm_compute(Ast + (c & 1) * ABUF, Wsm + (c & 1) * WBUF, acc, ty, tx);
        if (c < 3) {
            float* ad = Ast + ((c + 1) & 1) * ABUF;
            float* wd = Wsm + ((c + 1) & 1) * WBUF;
#pragma unroll
            for (int t = 0; t < 4; t++) {
                int idx = tid + t * 256;
                int r = idx >> 3, c4 = idx & 7;
                ad[(c4 * 4 + 0) * AP_ + r] = la[t].x;
                ad[(c4 * 4 + 1) * AP_ + r] = la[t].y;
                ad[(c4 * 4 + 2) * AP_ + r] = la[t].z;
                ad[(c4 * 4 + 3) * AP_ + r] = la[t].w;
                int wr = idx >> 5, wc = idx & 31;
                *(float4*)(wd + wr * 128 + wc * 4) = lw[t];
            }
            __syncthreads();
        }
    }

    float4 bv0 = *(const float4*)(bias + tx * 4);
    float4 bv1 = *(const float4*)(bias + 64 + tx * 4);
    float bb[8] = {bv0.x, bv0.y, bv0.z, bv0.w, bv1.x, bv1.y, bv1.z, bv1.w};

    if (MODE == 0) {
        float* orow = out + ((size_t)v * BT_ + bt0 + ty * 8) * H_;
#pragma unroll
        for (int i = 0; i < 8; i++) {
            float4 o0 = make_float4(acc[i][0] + bb[0], acc[i][1] + bb[1],
                                    acc[i][2] + bb[2], acc[i][3] + bb[3]);
            float4 o1 = make_float4(acc[i][4] + bb[4], acc[i][5] + bb[5],
                                    acc[i][6] + bb[6], acc[i][7] + bb[7]);
            *(float4*)(orow + (size_t)i * H_ + tx * 4) = o0;
            *(float4*)(orow + (size_t)i * H_ + 64 + tx * 4) = o1;
        }
    } else if (MODE == 1) {
        const float* g  = G  + (size_t)v * bstride;
        const float* nb = NB + (size_t)v * bstride;
        float4 g0 = *(const float4*)(g + tx * 4);
        float4 g1 = *(const float4*)(g + 64 + tx * 4);
        float4 n0 = *(const float4*)(nb + tx * 4);
        float4 n1 = *(const float4*)(nb + 64 + tx * 4);
        float gv[8] = {g0.x, g0.y, g0.z, g0.w, g1.x, g1.y, g1.z, g1.w};
        float nv[8] = {n0.x, n0.y, n0.z, n0.w, n1.x, n1.y, n1.z, n1.w};
        float* orow = out + ((size_t)v * BT_ + bt0 + ty * 8) * H_;
#pragma unroll
        for (int i = 0; i < 8; i++) {
            float vals[8];
            float s = 0.0f;
#pragma unroll
            for (int j = 0; j < 8; j++) { vals[j] = acc[i][j] + bb[j]; s += vals[j]; }
            s += __shfl_xor_sync(0xffffffffu, s, 8);
            s += __shfl_xor_sync(0xffffffffu, s, 4);
            s += __shfl_xor_sync(0xffffffffu, s, 2);
            s += __shfl_xor_sync(0xffffffffu, s, 1);
            float mu = s * (1.0f / H_);
            float sq = 0.0f;
#pragma unroll
            for (int j = 0; j < 8; j++) { vals[j] -= mu; sq += vals[j] * vals[j]; }
            sq += __shfl_xor_sync(0xffffffffu, sq, 8);
            sq += __shfl_xor_sync(0xffffffffu, sq, 4);
            sq += __shfl_xor_sync(0xffffffffu, sq, 2);
            sq += __shfl_xor_sync(0xffffffffu, sq, 1);
            float inv = rsqrtf(sq * (1.0f / H_) + 1e-5f);
            float y[8];
#pragma unroll
            for (int j = 0; j < 8; j++) {
                float t2 = vals[j] * inv * gv[j] + nv[j];
                y[j] = t2 * 0.5f * (1.0f + erff(t2 * 0.70710678118654752f));
            }
            *(float4*)(orow + (size_t)i * H_ + tx * 4) =
                make_float4(y[0], y[1], y[2], y[3]);
            *(float4*)(orow + (size_t)i * H_ + 64 + tx * 4) =
                make_float4(y[4], y[5], y[6], y[7]);
        }
    } else {
        float4 w0 = *(const float4*)(OW + (size_t)v * H_ + tx * 4);
        float4 w1 = *(const float4*)(OW + (size_t)v * H_ + 64 + tx * 4);
        float ow[8] = {w0.x, w0.y, w0.z, w0.w, w1.x, w1.y, w1.z, w1.w};
        float ob = OB[v];
#pragma unroll
        for (int i = 0; i < 8; i++) {
            float s = 0.0f;
#pragma unroll
            for (int j = 0; j < 8; j++) s += (acc[i][j] + bb[j]) * ow[j];
            s += __shfl_xor_sync(0xffffffffu, s, 8);
            s += __shfl_xor_sync(0xffffffffu, s, 4);
            s += __shfl_xor_sync(0xffffffffu, s, 2);
            s += __shfl_xor_sync(0xffffffffu, s, 1);
            if (tx == 0) PRED[(size_t)(bt0 + ty * 8 + i) * V_ + v] = s + ob;
        }
    }
}

// ---------------------------------------------------------------------------
// Kernel 3: attention per (b, v, head). 256 threads = 8 warps.
// Conflict-free: QK as outer-product over d with kT[d][key] (stride-1 lanes),
// AV with vT (stride 260 => phase banks 4d), psw per-warp 4-row buffer.
// Per warp-pass: 4 q rows; 8 passes cover 32 rows/warp.
// smem floats: qs 4096 + kT 4160 + vT 4160 + psw 8*4*260=8320  => 82944 B
// ---------------------------------------------------------------------------
#define KTP 260
#define ATTN_SMEM ((S_ * DH_ + 2 * DH_ * KTP + 8 * 4 * KTP) * 4)

__global__ __launch_bounds__(256, 2) void attn_kernel(
        const float* __restrict__ qg,
        const float* __restrict__ kg,
        const float* __restrict__ vg,
        float* __restrict__ og) {
    int id = blockIdx.x;
    int n  = id % NH_;
    int vv = (id / NH_) % V_;
    int b  = id / (NH_ * V_);
    int tid = threadIdx.x;

    extern __shared__ __align__(16) float asm_[];
    float* qs = asm_;                    // [256][16]
    float* kT = qs + S_ * DH_;           // [16][260]
    float* vT = kT + DH_ * KTP;          // [16][260]
    float* ps = vT + DH_ * KTP;          // [8 warps][4][260]

    size_t base = ((size_t)vv * BT_ + b * S_) * H_ + n * DH_;

    for (int e = tid; e < S_ * DH_; e += 256) {
        int t = e >> 4, d = e & 15;
        size_t g = base + (size_t)t * H_ + d;
        qs[t * DH_ + d] = qg[g];
        kT[d * KTP + t] = kg[g];
        vT[d * KTP + t] = vg[g];
    }
    __syncthreads();

    int w = tid >> 5, lane = tid & 31;
    float* psw = ps + w * 4 * KTP;

    for (int pass = 0; pass < 8; pass++) {
        int r0 = pass * 32 + w * 4;

        // ---- QK: acc[i][j] = score(row r0+i, key lane+32j) ----
        float acc[4][8];
#pragma unroll
        for (int i = 0; i < 4; i++)
#pragma unroll
            for (int j = 0; j < 8; j++) acc[i][j] = 0.0f;

#pragma unroll
        for (int d = 0; d < DH_; d++) {
            float kreg[8];
            const float* kr = kT + d * KTP + lane;
#pragma unroll
            for (int j = 0; j < 8; j++) kreg[j] = kr[j * 32];
            float q0 = qs[(r0 + 0) * DH_ + d];
            float q1 = qs[(r0 + 1) * DH_ + d];
            float q2 = qs[(r0 + 2) * DH_ + d];
            float q3 = qs[(r0 + 3) * DH_ + d];
#pragma unroll
            for (int j = 0; j < 8; j++) {
                acc[0][j] += q0 * kreg[j];
                acc[1][j] += q1 * kreg[j];
                acc[2][j] += q2 * kreg[j];
                acc[3][j] += q3 * kreg[j];
            }
        }

        // ---- softmax per row, p -> psw ----
        float invs[4];
#pragma unroll
        for (int i = 0; i < 4; i++) {
            float m = acc[i][0];
#pragma unroll
            for (int j = 1; j < 8; j++) m = fmaxf(m, acc[i][j]);
            m *= 0.25f;
#pragma unroll
            for (int off = 16; off; off >>= 1)
                m = fmaxf(m, __shfl_xor_sync(0xffffffffu, m, off));
            float lsum = 0.0f;
            float p[8];
#pragma unroll
            for (int j = 0; j < 8; j++) {
                p[j] = __expf(acc[i][j] * 0.25f - m);
                lsum += p[j];
            }
#pragma unroll
            for (int off = 16; off; off >>= 1)
                lsum += __shfl_xor_sync(0xffffffffu, lsum, off);
            invs[i] = 1.0f / lsum;
            float* prow = psw + i * KTP + lane;
#pragma unroll
            for (int j = 0; j < 8; j++) prow[j * 32] = p[j];
        }
        __syncwarp();

        // ---- AV: lane=(d, half). o[i] = sum_key p[i][key] * vT[d][key] ----
        int d = lane & 15;
        int half = lane >> 4;
        const float* vrow = vT + d * KTP + half * 128;
        const float* p0 = psw + 0 * KTP + half * 128;
        const float* p1 = psw + 1 * KTP + half * 128;
        const float* p2 = psw + 2 * KTP + half * 128;
        const float* p3 = psw + 3 * KTP + half * 128;
        float o0 = 0.f, o1 = 0.f, o2 = 0.f, o3 = 0.f;
#pragma unroll 8
        for (int it = 0; it < 32; it++) {
            float4 vv4 = *(const float4*)(vrow + it * 4);
            float4 a0 = *(const float4*)(p0 + it * 4);
            float4 a1 = *(const float4*)(p1 + it * 4);
            float4 a2 = *(const float4*)(p2 + it * 4);
            float4 a3 = *(const float4*)(p3 + it * 4);
            o0 += a0.x * vv4.x + a0.y * vv4.y + a0.z * vv4.z + a0.w * vv4.w;
            o1 += a1.x * vv4.x + a1.y * vv4.y + a1.z * vv4.z + a1.w * vv4.w;
            o2 += a2.x * vv4.x + a2.y * vv4.y + a2.z * vv4.z + a2.w * vv4.w;
            o3 += a3.x * vv4.x + a3.y * vv4.y + a3.z * vv4.z + a3.w * vv4.w;
        }
        o0 += __shfl_xor_sync(0xffffffffu, o0, 16);
        o1 += __shfl_xor_sync(0xffffffffu, o1, 16);
        o2 += __shfl_xor_sync(0xffffffffu, o2, 16);
        o3 += __shfl_xor_sync(0xffffffffu, o3, 16);
        if (lane < 16) {
            og[base + (size_t)(r0 + 0) * H_ + d] = o0 * invs[0];
            og[base + (size_t)(r0 + 1) * H_ + d] = o1 * invs[1];
            og[base + (size_t)(r0 + 2) * H_ + d] = o2 * invs[2];
            og[base + (size_t)(r0 + 3) * H_ + d] = o3 * invs[3];
        }
        __syncwarp();
    }
}

// ---------------------------------------------------------------------------
// Launch
// ---------------------------------------------------------------------------
extern "C" void kernel_launch(void* const* d_in, const int* in_sizes, int n_in,
                              void* d_out, int out_size) {
    const float* x       = (const float*)d_in[0];
    const float* adj_l   = (const float*)d_in[1];
    const float* var_emb = (const float*)d_in[2];
    const float* temp_emb= (const float*)d_in[3];
    const float* mech_W  = (const float*)d_in[4];
    const float* mech_b  = (const float*)d_in[5];
    const float* ln_g    = (const float*)d_in[6];
    const float* ln_b    = (const float*)d_in[7];
    const float* Wq      = (const float*)d_in[8];
    const float* Wk      = (const float*)d_in[9];
    const float* Wv      = (const float*)d_in[10];
    const float* Wo      = (const float*)d_in[11];
    const float* bq      = (const float*)d_in[12];
    const float* bk      = (const float*)d_in[13];
    const float* bv      = (const float*)d_in[14];
    const float* bo      = (const float*)d_in[15];
    const float* out_W   = (const float*)d_in[16];
    const float* out_b   = (const float*)d_in[17];
    float* pred = (float*)d_out;

    float *zA, *zB, *qb, *kb, *vb;
    cudaGetSymbolAddress((void**)&zA, g_zA);
    cudaGetSymbolAddress((void**)&zB, g_zB);
    cudaGetSymbolAddress((void**)&qb, g_qb);
    cudaGetSymbolAddress((void**)&kb, g_kb);
    cudaGetSymbolAddress((void**)&vb, g_vb);

    cudaFuncSetAttribute((const void*)gemm2<0>,
                         cudaFuncAttributeMaxDynamicSharedMemorySize, GEMM_SMEM);
    cudaFuncSetAttribute((const void*)gemm2<1>,
                         cudaFuncAttributeMaxDynamicSharedMemorySize, GEMM_SMEM);
    cudaFuncSetAttribute((const void*)gemm2<2>,
                         cudaFuncAttributeMaxDynamicSharedMemorySize, GEMM_SMEM);
    cudaFuncSetAttribute((const void*)causal_kernel,
                         cudaFuncAttributeMaxDynamicSharedMemorySize, CAU_SMEM);
    cudaFuncSetAttribute((const void*)attn_kernel,
                         cudaFuncAttributeMaxDynamicSharedMemorySize, ATTN_SMEM);

    sigmoid_kernel<<<(V_ * V_ * LP1_ + 255) / 256, 256>>>(adj_l);
    causal_kernel<<<BT_, 256, CAU_SMEM>>>(x, var_emb, temp_emb, zA);

    dim3 ggrid(BT_ / 128, V_, 1);
    const int WS = NL_ * H_ * H_, BS = NL_ * H_;
    gemm2<1><<<ggrid, 256, GEMM_SMEM>>>(zA,
        mech_W + 0 * H_ * H_, nullptr, nullptr,
        mech_b + 0 * H_, nullptr, nullptr,
        ln_g + 0 * H_, ln_b + 0 * H_,
        zB, nullptr, nullptr, nullptr, nullptr, nullptr, WS, BS);
    gemm2<1><<<ggrid, 256, GEMM_SMEM>>>(zB,
        mech_W + 1 * H_ * H_, nullptr, nullptr,
        mech_b + 1 * H_, nullptr, nullptr,
        ln_g + 1 * H_, ln_b + 1 * H_,
        zA, nullptr, nullptr, nullptr, nullptr, nullptr, WS, BS);
    gemm2<1><<<ggrid, 256, GEMM_SMEM>>>(zA,
        mech_W + 2 * H_ * H_, nullptr, nullptr,
        mech_b + 2 * H_, nullptr, nullptr,
        ln_g + 2 * H_, ln_b + 2 * H_,
        zB, nullptr, nullptr, nullptr, nullptr, nullptr, WS, BS);

    dim3 qkvgrid(BT_ / 128, V_, 3);
    gemm2<0><<<qkvgrid, 256, GEMM_SMEM>>>(zB,
        Wq, Wk, Wv, bq, bk, bv, nullptr, nullptr,
        qb, kb, vb, nullptr, nullptr, nullptr, H_ * H_, H_);

    attn_kernel<<<B_ * V_ * NH_, 256, ATTN_SMEM>>>(qb, kb, vb, zA);

    gemm2<2><<<ggrid, 256, GEMM_SMEM>>>(zA,
        Wo, nullptr, nullptr, bo, nullptr, nullptr, nullptr, nullptr,
        nullptr, nullptr, nullptr, out_W, out_b, pred, H_ * H_, H_);
}